// round 6
// baseline (speedup 1.0000x reference)
#include <cuda_runtime.h>
#include <cuda_fp16.h>
#include <cstdint>

// ============================================================================
// TernaryLinear: out[8192,4096] = x[8192,4096] @ (ternary(w)[4096,4096]).T
//
// out = (x @ q^T) * scale[col], q in {-1,0,1} exact in fp16; x -> fp16
// (u=2^-11 => ~3.5e-4 rel err, measured). fp32 accumulate in registers.
//
// R6: barrier-free mainloop. cp.async completion tracked by mbarriers
// (cp.async.mbarrier.arrive.noinc, 128 arrivals = stage resident); stage
// reuse gated by empty[] mbarriers (arrive after last read). No
// __syncthreads / wait_group in the K loop -> warps gate on data readiness,
// not on sibling-warp convergence. Next-stage loads issued after first MMA
// block. 2 CTAs/SM x 128 threads, 128x128 tiles, 3 stages, 64x64 warp
// tiles, cross-chunk ldmatrix prefetch, register frag double-buffering.
// ============================================================================

#define DINLINE __device__ __forceinline__

static constexpr int M = 8192, N = 4096, K = 4096;
static constexpr int BM = 128, BN = 128, BK = 64;
static constexpr int CHUNKS = K / BK;                  // 64
static constexpr int STAGES = 3;
static constexpr int STAGE_BYTES = (BM + BN) * BK * 2; // 32768
static constexpr int SMEM_STAGE0 = 1024;               // barriers live below
static constexpr int SMEM_SIZE = SMEM_STAGE0 + STAGES * STAGE_BYTES; // 99328

// scratch (device globals: allocation-free)
__device__ __half g_q[(size_t)N * K];     // ternary weights, fp16 exact
__device__ __half g_xh[(size_t)M * K];    // x in fp16
__device__ float  g_scale[N];

// ---------------------------------------------------------------------------
// helpers
// ---------------------------------------------------------------------------
DINLINE uint32_t smem_u32(const void* p) {
    uint32_t a;
    asm("{ .reg .u64 t; cvta.to.shared.u64 t, %1; cvt.u32.u64 %0, t; }" : "=r"(a) : "l"(p));
    return a;
}
DINLINE void cp16(uint32_t dst, const void* src) {
    asm volatile("cp.async.cg.shared.global [%0], [%1], 16;" :: "r"(dst), "l"(src));
}
DINLINE void cp_mbar_arrive(uint32_t mbar) {
    asm volatile("cp.async.mbarrier.arrive.noinc.shared.b64 [%0];" :: "r"(mbar) : "memory");
}
#define MBAR_INIT(a, c) asm volatile("mbarrier.init.shared.b64 [%0], %1;" :: "r"(a), "r"(c) : "memory")
#define MBAR_ARRIVE(a)  asm volatile("mbarrier.arrive.shared.b64 _, [%0];" :: "r"(a) : "memory")
#define MBAR_WAIT(a, ph) do {                                                     \
    uint32_t _m = (a), _p = (ph), _d;                                             \
    asm volatile("{ .reg .pred p; mbarrier.try_wait.parity.acquire.cta.shared::cta.b64 p, [%1], %2; selp.b32 %0,1,0,p; }" \
        : "=r"(_d) : "r"(_m), "r"(_p) : "memory");                                \
    if (!_d) {                                                                    \
        asm volatile("{ .reg .pred P1; W%=: mbarrier.try_wait.parity.acquire.cta.shared::cta.b64 P1, [%0], %1, 0x989680; @P1 bra.uni D%=; bra.uni W%=; D%=: }" \
            :: "r"(_m), "r"(_p) : "memory");                                      \
    }                                                                             \
} while (0)

DINLINE void ldsm4(uint32_t* r, uint32_t addr) {
    asm volatile("ldmatrix.sync.aligned.m8n8.x4.shared.b16 {%0,%1,%2,%3}, [%4];"
                 : "=r"(r[0]), "=r"(r[1]), "=r"(r[2]), "=r"(r[3]) : "r"(addr));
}
DINLINE void mma16816(float* c, const uint32_t* a, const uint32_t* b) {
    asm volatile(
        "mma.sync.aligned.m16n8k16.row.col.f32.f16.f16.f32 "
        "{%0,%1,%2,%3}, {%4,%5,%6,%7}, {%8,%9}, {%0,%1,%2,%3};"
        : "+f"(c[0]), "+f"(c[1]), "+f"(c[2]), "+f"(c[3])
        : "r"(a[0]), "r"(a[1]), "r"(a[2]), "r"(a[3]), "r"(b[0]), "r"(b[1]));
}

// ---------------------------------------------------------------------------
// Fused prep: blocks [0, N) quantize w rows (one-pass, row in registers);
// blocks [N, N + M*K/2048) convert x to fp16.
// ---------------------------------------------------------------------------
__global__ void __launch_bounds__(256) prep_kernel(const float* __restrict__ w,
                                                   const float* __restrict__ x) {
    if (blockIdx.x < (unsigned)N) {
        const int row = blockIdx.x, tid = threadIdx.x;
        const float4* wr = reinterpret_cast<const float4*>(w + (size_t)row * K);
        float4 v[4];
        float s = 0.f;
        #pragma unroll
        for (int t = 0; t < 4; t++) {
            v[t] = wr[tid + 256 * t];
            s += fabsf(v[t].x) + fabsf(v[t].y) + fabsf(v[t].z) + fabsf(v[t].w);
        }
        for (int o = 16; o; o >>= 1) s += __shfl_xor_sync(~0u, s, o);
        __shared__ float warp_s[8];
        __shared__ float sc;
        if ((tid & 31) == 0) warp_s[tid >> 5] = s;
        __syncthreads();
        if (tid == 0) {
            float t = 0.f;
            for (int i = 0; i < 8; i++) t += warp_s[i];
            float m = t * (1.f / (float)K);
            if (m < 1e-5f) m = 1e-5f;
            sc = m;
            g_scale[row] = m;
        }
        __syncthreads();
        const float inv = 1.f / sc;
        __half2* qr = reinterpret_cast<__half2*>(g_q + (size_t)row * K);
        #pragma unroll
        for (int t = 0; t < 4; t++) {
            float q0 = fminf(fmaxf(rintf(v[t].x * inv), -1.f), 1.f);
            float q1 = fminf(fmaxf(rintf(v[t].y * inv), -1.f), 1.f);
            float q2 = fminf(fmaxf(rintf(v[t].z * inv), -1.f), 1.f);
            float q3 = fminf(fmaxf(rintf(v[t].w * inv), -1.f), 1.f);
            qr[2 * (tid + 256 * t)]     = __floats2half2_rn(q0, q1);
            qr[2 * (tid + 256 * t) + 1] = __floats2half2_rn(q2, q3);
        }
    } else {
        size_t i = (size_t)(blockIdx.x - N) * 256 + threadIdx.x;  // 8 floats each
        const float4* x4 = reinterpret_cast<const float4*>(x);
        float4 a = x4[2 * i], b = x4[2 * i + 1];
        __half2 h0 = __floats2half2_rn(a.x, a.y);
        __half2 h1 = __floats2half2_rn(a.z, a.w);
        __half2 h2 = __floats2half2_rn(b.x, b.y);
        __half2 h3 = __floats2half2_rn(b.z, b.w);
        uint4 o;
        o.x = *reinterpret_cast<uint32_t*>(&h0);
        o.y = *reinterpret_cast<uint32_t*>(&h1);
        o.z = *reinterpret_cast<uint32_t*>(&h2);
        o.w = *reinterpret_cast<uint32_t*>(&h3);
        reinterpret_cast<uint4*>(g_xh)[i] = o;
    }
}

// ---------------------------------------------------------------------------
// GEMM: CTA 128x128, BK=64, 3-stage mbarrier pipeline (no loop barriers),
// 4 warps (2m x 2n), 2 CTAs/SM. Warp tile 64x64 via mma.sync.m16n8k16,
// register frag double-buffering with cross-chunk prefetch.
// Smem rows = 64 halves (128B), xor swizzle: chunk c -> c ^ (row & 7).
// mbarriers: full[s] (cp.async arrive-on-complete x128), empty[s]
// (explicit arrive x128 after last read of stage s).
// ---------------------------------------------------------------------------
__global__ void __launch_bounds__(128, 2) gemm_kernel(
    const __half* __restrict__ A,   // [M,K] fp16
    const __half* __restrict__ B,   // [N,K] fp16 ternary
    float* __restrict__ out)        // [M,N] fp32
{
    extern __shared__ char smem[];
    const uint32_t sbase = smem_u32(smem);
    const int tid = threadIdx.x, lane = tid & 31, wid = tid >> 5;
    const int wm = wid >> 1, wn = wid & 1;     // warp tile: (wm*64, wn*64)
    const int mrow = blockIdx.y * BM;
    const int nbase = blockIdx.x * BN;

    // barriers: full[0..2] at sbase+0,16,32 ; empty[0..2] at sbase+48,64,80
    const uint32_t FULL = sbase, EMPTY = sbase + 48;
    const uint32_t STAGE0 = sbase + SMEM_STAGE0;

    if (tid == 0) {
        #pragma unroll
        for (int s = 0; s < 3; s++) {
            MBAR_INIT(FULL + 16 * s, 128);
            MBAR_INIT(EMPTY + 16 * s, 128);
        }
    }
    __syncthreads();

    float acc[4][8][4];
    #pragma unroll
    for (int i = 0; i < 4; i++)
        #pragma unroll
        for (int j = 0; j < 8; j++)
            #pragma unroll
            for (int k = 0; k < 4; k++) acc[i][j][k] = 0.f;

    // cp.async coords: 16 rows/iter across 128 threads, 8 x 16B chunks per row
    const int ldrow = tid >> 3;          // 0..15
    const int ldc   = tid & 7;
    // ldmatrix lane coords
    const int arow = lane & 15, asel = lane >> 4;
    const int brow = (lane & 7) + ((lane >> 4) << 3), bsel = (lane >> 3) & 1;
    const int axor = arow & 7, bxor = brow & 7;

    auto load_stage = [&](int s, int kc) {
        const uint32_t sA = STAGE0 + s * STAGE_BYTES;
        const uint32_t sB = sA + BM * 128;
        const size_t kof = (size_t)kc * BK + ldc * 8;
        #pragma unroll
        for (int it = 0; it < 8; it++) {
            const int row = it * 16 + ldrow;
            cp16(sA + row * 128 + ((ldc ^ (row & 7)) << 4),
                 A + (size_t)(mrow + row) * K + kof);
        }
        #pragma unroll
        for (int it = 0; it < 8; it++) {
            const int row = it * 16 + ldrow;
            cp16(sB + row * 128 + ((ldc ^ (row & 7)) << 4),
                 B + (size_t)(nbase + row) * K + kof);
        }
        cp_mbar_arrive(FULL + 16 * s);
    };

    uint32_t af[2][4][4], bf[2][4][4];

    auto load_frags = [&](int s, int ks, int buf) {
        const uint32_t aB = STAGE0 + s * STAGE_BYTES;
        const uint32_t bB = aB + BM * 128;
        #pragma unroll
        for (int mt = 0; mt < 4; mt++) {
            const int row = wm * 64 + mt * 16 + arow;
            ldsm4(af[buf][mt], aB + row * 128 + (((ks * 2 + asel) ^ axor) << 4));
        }
        #pragma unroll
        for (int p = 0; p < 4; p++) {
            const int row = wn * 64 + p * 16 + brow;
            ldsm4(bf[buf][p], bB + row * 128 + (((ks * 2 + bsel) ^ bxor) << 4));
        }
    };

    // prologue: chunks 0 and 1 in flight; wait chunk 0, prefetch frags(0,0)
    load_stage(0, 0);
    load_stage(1, 1);
    MBAR_WAIT(FULL + 0, 0);
    load_frags(0, 0, 0);

    for (int i = 0; i < CHUNKS; i++) {
        const int scur = i % STAGES;

        #pragma unroll
        for (int ks = 0; ks < 4; ks++) {
            const int b = ks & 1;
            if (ks == 1 && i + 2 < CHUNKS) {
                // load chunk i+2 into stage (i+2)%3; WAR-gate on empty
                const int s2 = (i + 2) % STAGES;
                if (i + 2 >= STAGES) {
                    MBAR_WAIT(EMPTY + 16 * s2, (((i + 2) / 3) - 1) & 1);
                }
                load_stage(s2, i + 2);
            }
            if (ks < 3) {
                load_frags(scur, ks + 1, b ^ 1);
            } else if (i + 1 < CHUNKS) {
                const int s1 = (i + 1) % STAGES;
                MBAR_WAIT(FULL + 16 * s1, ((i + 1) / 3) & 1);
                load_frags(s1, 0, b ^ 1);
            }
            #pragma unroll
            for (int mt = 0; mt < 4; mt++)
                #pragma unroll
                for (int nt = 0; nt < 8; nt++)
                    mma16816(acc[mt][nt], af[b][mt], bf[b][nt >> 1] + (nt & 1) * 2);
        }
        // all reads of stage scur complete (last ldsm consumed by ks=3 mma)
        MBAR_ARRIVE(EMPTY + 16 * scur);
    }

    // epilogue: scale columns, write fp32
    const int g = lane >> 2, qn = lane & 3;
    #pragma unroll
    for (int nt = 0; nt < 8; nt++) {
        const int col = wn * 64 + nt * 8 + qn * 2;
        const float2 s2 = *reinterpret_cast<const float2*>(&g_scale[nbase + col]);
        #pragma unroll
        for (int mt = 0; mt < 4; mt++) {
            const int row0 = mrow + wm * 64 + mt * 16 + g;
            float2 v0 = { acc[mt][nt][0] * s2.x, acc[mt][nt][1] * s2.y };
            float2 v1 = { acc[mt][nt][2] * s2.x, acc[mt][nt][3] * s2.y };
            *reinterpret_cast<float2*>(out + (size_t)row0 * N + nbase + col) = v0;
            *reinterpret_cast<float2*>(out + (size_t)(row0 + 8) * N + nbase + col) = v1;
        }
    }
}

// ---------------------------------------------------------------------------
// Host launch
// ---------------------------------------------------------------------------
extern "C" void kernel_launch(void* const* d_in, const int* in_sizes, int n_in,
                              void* d_out, int out_size) {
    const float* x = (const float*)d_in[0];   // [8192, 4096]
    const float* w = (const float*)d_in[1];   // [4096, 4096]
    float* out = (float*)d_out;               // [8192, 4096]

    void *p_q = nullptr, *p_xh = nullptr;
    cudaGetSymbolAddress(&p_q, g_q);
    cudaGetSymbolAddress(&p_xh, g_xh);

    cudaFuncSetAttribute(gemm_kernel, cudaFuncAttributeMaxDynamicSharedMemorySize, SMEM_SIZE);

    const int conv_blocks = (int)(((size_t)M * K / 8) / 256);  // 16384
    prep_kernel<<<N + conv_blocks, 256>>>(w, x);
    gemm_kernel<<<dim3(N / BN, M / BM), 128, SMEM_SIZE>>>(
        (const __half*)p_xh, (const __half*)p_q, out);
}

// round 7
// speedup vs baseline: 1.0501x; 1.0501x over previous
#include <cuda_runtime.h>
#include <cuda.h>
#include <cuda_fp16.h>
#include <cstdint>

// ============================================================================
// TernaryLinear: out[8192,4096] = x[8192,4096] @ (ternary(w)[4096,4096]).T
//
// out = (x @ q^T) * scale[col], q in {-1,0,1} exact in fp16; x -> fp16
// (u=2^-11 => ~3.5e-4 rel err, measured). fp32 accumulate in registers.
//
// R7: TMA stage loads. R6 ledger showed LSU at 100% (cp.async 256cyc +
// LDSM 256cyc per 512-cyc SMSP window) while tensor sat at 84%. Replace the
// per-thread cp.async burst with 2 TMA bulk loads per stage issued by one
// elected thread (rotating warp). TMA SW128 swizzle == our ldmatrix xor
// swizzle on 128B rows, so consumer addressing is unchanged. mbarrier
// pipeline: full[s] = count1 + expect_tx(32KB); empty[s] = 128 arrivals.
// 2 CTAs/SM x 128 threads, 128x128 tiles, 3 stages, 64x64 warp tiles,
// cross-chunk ldmatrix prefetch, register frag double-buffering.
// ============================================================================

#define DINLINE __device__ __forceinline__

static constexpr int M = 8192, N = 4096, K = 4096;
static constexpr int BM = 128, BN = 128, BK = 64;
static constexpr int CHUNKS = K / BK;                  // 64
static constexpr int STAGES = 3;
static constexpr int STAGE_BYTES = (BM + BN) * BK * 2; // 32768
static constexpr int SMEM_STAGE0 = 1024;               // barriers live below
static constexpr int SMEM_SIZE = SMEM_STAGE0 + STAGES * STAGE_BYTES; // 99328

// scratch (device globals: allocation-free)
__device__ __half g_q[(size_t)N * K];     // ternary weights, fp16 exact
__device__ __half g_xh[(size_t)M * K];    // x in fp16
__device__ float  g_scale[N];

// ---------------------------------------------------------------------------
// helpers
// ---------------------------------------------------------------------------
DINLINE uint32_t smem_u32(const void* p) {
    uint32_t a;
    asm("{ .reg .u64 t; cvta.to.shared.u64 t, %1; cvt.u32.u64 %0, t; }" : "=r"(a) : "l"(p));
    return a;
}
DINLINE uint32_t elect_one() {
    uint32_t p;
    asm volatile("{ .reg .pred p; elect.sync _|p, 0xFFFFFFFF; selp.b32 %0, 1, 0, p; }" : "=r"(p));
    return p;
}
#define MBAR_INIT(a, c) asm volatile("mbarrier.init.shared.b64 [%0], %1;" :: "r"(a), "r"(c) : "memory")
#define MBAR_ARRIVE(a)  asm volatile("mbarrier.arrive.shared.b64 _, [%0];" :: "r"(a) : "memory")
#define MBAR_EXPECT_TX(a, b) asm volatile("mbarrier.arrive.expect_tx.shared.b64 _, [%0], %1;" :: "r"(a), "r"(b) : "memory")
#define MBAR_WAIT(a, ph) do {                                                     \
    uint32_t _m = (a), _p = (ph), _d;                                             \
    asm volatile("{ .reg .pred p; mbarrier.try_wait.parity.acquire.cta.shared::cta.b64 p, [%1], %2; selp.b32 %0,1,0,p; }" \
        : "=r"(_d) : "r"(_m), "r"(_p) : "memory");                                \
    if (!_d) {                                                                    \
        asm volatile("{ .reg .pred P1; W%=: mbarrier.try_wait.parity.acquire.cta.shared::cta.b64 P1, [%0], %1, 0x989680; @P1 bra.uni D%=; bra.uni W%=; D%=: }" \
            :: "r"(_m), "r"(_p) : "memory");                                      \
    }                                                                             \
} while (0)

#define TMA_LOAD_2D(smem, map, cx, cy, mbar)                                      \
    asm volatile("cp.async.bulk.tensor.2d.shared::cta.global.tile.mbarrier::complete_tx::bytes [%0], [%1, {%2, %3}], [%4];" \
        :: "r"(smem), "l"(map), "r"(cx), "r"(cy), "r"(mbar) : "memory")

DINLINE void ldsm4(uint32_t* r, uint32_t addr) {
    asm volatile("ldmatrix.sync.aligned.m8n8.x4.shared.b16 {%0,%1,%2,%3}, [%4];"
                 : "=r"(r[0]), "=r"(r[1]), "=r"(r[2]), "=r"(r[3]) : "r"(addr));
}
DINLINE void mma16816(float* c, const uint32_t* a, const uint32_t* b) {
    asm volatile(
        "mma.sync.aligned.m16n8k16.row.col.f32.f16.f16.f32 "
        "{%0,%1,%2,%3}, {%4,%5,%6,%7}, {%8,%9}, {%0,%1,%2,%3};"
        : "+f"(c[0]), "+f"(c[1]), "+f"(c[2]), "+f"(c[3])
        : "r"(a[0]), "r"(a[1]), "r"(a[2]), "r"(a[3]), "r"(b[0]), "r"(b[1]));
}

// ---------------------------------------------------------------------------
// Fused prep: blocks [0, N) quantize w rows (one-pass, row in registers);
// blocks [N, N + M*K/2048) convert x to fp16.
// ---------------------------------------------------------------------------
__global__ void __launch_bounds__(256) prep_kernel(const float* __restrict__ w,
                                                   const float* __restrict__ x) {
    if (blockIdx.x < (unsigned)N) {
        const int row = blockIdx.x, tid = threadIdx.x;
        const float4* wr = reinterpret_cast<const float4*>(w + (size_t)row * K);
        float4 v[4];
        float s = 0.f;
        #pragma unroll
        for (int t = 0; t < 4; t++) {
            v[t] = wr[tid + 256 * t];
            s += fabsf(v[t].x) + fabsf(v[t].y) + fabsf(v[t].z) + fabsf(v[t].w);
        }
        for (int o = 16; o; o >>= 1) s += __shfl_xor_sync(~0u, s, o);
        __shared__ float warp_s[8];
        __shared__ float sc;
        if ((tid & 31) == 0) warp_s[tid >> 5] = s;
        __syncthreads();
        if (tid == 0) {
            float t = 0.f;
            for (int i = 0; i < 8; i++) t += warp_s[i];
            float m = t * (1.f / (float)K);
            if (m < 1e-5f) m = 1e-5f;
            sc = m;
            g_scale[row] = m;
        }
        __syncthreads();
        const float inv = 1.f / sc;
        __half2* qr = reinterpret_cast<__half2*>(g_q + (size_t)row * K);
        #pragma unroll
        for (int t = 0; t < 4; t++) {
            float q0 = fminf(fmaxf(rintf(v[t].x * inv), -1.f), 1.f);
            float q1 = fminf(fmaxf(rintf(v[t].y * inv), -1.f), 1.f);
            float q2 = fminf(fmaxf(rintf(v[t].z * inv), -1.f), 1.f);
            float q3 = fminf(fmaxf(rintf(v[t].w * inv), -1.f), 1.f);
            qr[2 * (tid + 256 * t)]     = __floats2half2_rn(q0, q1);
            qr[2 * (tid + 256 * t) + 1] = __floats2half2_rn(q2, q3);
        }
    } else {
        size_t i = (size_t)(blockIdx.x - N) * 256 + threadIdx.x;  // 8 floats each
        const float4* x4 = reinterpret_cast<const float4*>(x);
        float4 a = x4[2 * i], b = x4[2 * i + 1];
        __half2 h0 = __floats2half2_rn(a.x, a.y);
        __half2 h1 = __floats2half2_rn(a.z, a.w);
        __half2 h2 = __floats2half2_rn(b.x, b.y);
        __half2 h3 = __floats2half2_rn(b.z, b.w);
        uint4 o;
        o.x = *reinterpret_cast<uint32_t*>(&h0);
        o.y = *reinterpret_cast<uint32_t*>(&h1);
        o.z = *reinterpret_cast<uint32_t*>(&h2);
        o.w = *reinterpret_cast<uint32_t*>(&h3);
        reinterpret_cast<uint4*>(g_xh)[i] = o;
    }
}

// ---------------------------------------------------------------------------
// GEMM: CTA 128x128, BK=64, 3-stage TMA+mbarrier pipeline, 4 warps (2m x 2n),
// 2 CTAs/SM. Warp tile 64x64 via mma.sync.m16n8k16, register frag
// double-buffering with cross-chunk prefetch.
// Smem rows = 64 halves (128B); TMA SW128 swizzle == c ^ (row & 7) on 16B
// chunks, matching the ldmatrix addressing below.
// ---------------------------------------------------------------------------
__global__ void __launch_bounds__(128, 2) gemm_kernel(
    const __grid_constant__ CUtensorMap tmA,
    const __grid_constant__ CUtensorMap tmB,
    float* __restrict__ out)        // [M,N] fp32
{
    extern __shared__ char smem[];
    const uint32_t sbase = smem_u32(smem);
    const int tid = threadIdx.x, lane = tid & 31, wid = tid >> 5;
    const int wm = wid >> 1, wn = wid & 1;     // warp tile: (wm*64, wn*64)
    const int mrow = blockIdx.y * BM;
    const int nbase = blockIdx.x * BN;

    // barriers: full[0..2] at sbase+0,16,32 ; empty[0..2] at sbase+48,64,80
    const uint32_t FULL = sbase, EMPTY = sbase + 48;
    const uint32_t STAGE0 = sbase + SMEM_STAGE0;

    if (tid == 0) {
        #pragma unroll
        for (int s = 0; s < 3; s++) {
            MBAR_INIT(FULL + 16 * s, 1);
            MBAR_INIT(EMPTY + 16 * s, 128);
        }
    }
    __syncthreads();

    float acc[4][8][4];
    #pragma unroll
    for (int i = 0; i < 4; i++)
        #pragma unroll
        for (int j = 0; j < 8; j++)
            #pragma unroll
            for (int k = 0; k < 4; k++) acc[i][j][k] = 0.f;

    // ldmatrix lane coords
    const int arow = lane & 15, asel = lane >> 4;
    const int brow = (lane & 7) + ((lane >> 4) << 3), bsel = (lane >> 3) & 1;
    const int axor = arow & 7, bxor = brow & 7;

    // TMA stage issue (caller must be warp-uniform; elected lane only)
    auto issue_stage = [&](int s, int kc) {
        const uint32_t sA = STAGE0 + s * STAGE_BYTES;
        MBAR_EXPECT_TX(FULL + 16 * s, (uint32_t)STAGE_BYTES);
        TMA_LOAD_2D(sA,            &tmA, kc * BK, mrow,  FULL + 16 * s);
        TMA_LOAD_2D(sA + BM * 128, &tmB, kc * BK, nbase, FULL + 16 * s);
    };

    uint32_t af[2][4][4], bf[2][4][4];

    auto load_frags = [&](int s, int ks, int buf) {
        const uint32_t aB = STAGE0 + s * STAGE_BYTES;
        const uint32_t bB = aB + BM * 128;
        #pragma unroll
        for (int mt = 0; mt < 4; mt++) {
            const int row = wm * 64 + mt * 16 + arow;
            ldsm4(af[buf][mt], aB + row * 128 + (((ks * 2 + asel) ^ axor) << 4));
        }
        #pragma unroll
        for (int p = 0; p < 4; p++) {
            const int row = wn * 64 + p * 16 + brow;
            ldsm4(bf[buf][p], bB + row * 128 + (((ks * 2 + bsel) ^ bxor) << 4));
        }
    };

    // prologue: issue chunks 0 and 1; wait chunk 0; prefetch frags(0,0)
    if (wid == 0 && elect_one()) {
        issue_stage(0, 0);
        issue_stage(1, 1);
    }
    MBAR_WAIT(FULL + 0, 0);
    load_frags(0, 0, 0);

    for (int i = 0; i < CHUNKS; i++) {
        const int scur = i % STAGES;

        #pragma unroll
        for (int ks = 0; ks < 4; ks++) {
            const int b = ks & 1;
            if (ks == 1 && i + 2 < CHUNKS) {
                // rotate TMA-issue duty across warps; WAR-gate on empty
                if (wid == ((i + 2) & 3)) {
                    if (elect_one()) {
                        const int s2 = (i + 2) % STAGES;
                        if (i + 2 >= STAGES) {
                            MBAR_WAIT(EMPTY + 16 * s2, (((i + 2) / 3) - 1) & 1);
                        }
                        issue_stage(s2, i + 2);
                    }
                }
            }
            if (ks < 3) {
                load_frags(scur, ks + 1, b ^ 1);
            } else if (i + 1 < CHUNKS) {
                const int s1 = (i + 1) % STAGES;
                MBAR_WAIT(FULL + 16 * s1, ((i + 1) / 3) & 1);
                load_frags(s1, 0, b ^ 1);
            }
            #pragma unroll
            for (int mt = 0; mt < 4; mt++)
                #pragma unroll
                for (int nt = 0; nt < 8; nt++)
                    mma16816(acc[mt][nt], af[b][mt], bf[b][nt >> 1] + (nt & 1) * 2);
        }
        // all reads of stage scur complete (last ldsm consumed by ks=3 mma)
        MBAR_ARRIVE(EMPTY + 16 * scur);
    }

    // epilogue: scale columns, write fp32
    const int g = lane >> 2, qn = lane & 3;
    #pragma unroll
    for (int nt = 0; nt < 8; nt++) {
        const int col = wn * 64 + nt * 8 + qn * 2;
        const float2 s2 = *reinterpret_cast<const float2*>(&g_scale[nbase + col]);
        #pragma unroll
        for (int mt = 0; mt < 4; mt++) {
            const int row0 = mrow + wm * 64 + mt * 16 + g;
            float2 v0 = { acc[mt][nt][0] * s2.x, acc[mt][nt][1] * s2.y };
            float2 v1 = { acc[mt][nt][2] * s2.x, acc[mt][nt][3] * s2.y };
            *reinterpret_cast<float2*>(out + (size_t)row0 * N + nbase + col) = v0;
            *reinterpret_cast<float2*>(out + (size_t)(row0 + 8) * N + nbase + col) = v1;
        }
    }
}

// ---------------------------------------------------------------------------
// Host launch
// ---------------------------------------------------------------------------
typedef CUresult (*PFN_tmEnc)(CUtensorMap*, CUtensorMapDataType, cuuint32_t, void*,
                              const cuuint64_t*, const cuuint64_t*, const cuuint32_t*,
                              const cuuint32_t*, CUtensorMapInterleave, CUtensorMapSwizzle,
                              CUtensorMapL2promotion, CUtensorMapFloatOOBfill);

static void make2d(PFN_tmEnc enc, CUtensorMap* tm, void* ptr, uint64_t rows) {
    cuuint64_t dims[2] = {(cuuint64_t)K, rows};
    cuuint64_t strides[1] = {(cuuint64_t)K * 2};
    cuuint32_t box[2] = {64, 128};          // 64 halves = 128B x 128 rows
    cuuint32_t es[2] = {1, 1};
    enc(tm, CU_TENSOR_MAP_DATA_TYPE_BFLOAT16 /* 2-byte elems; layout-only */,
        2, ptr, dims, strides, box, es,
        CU_TENSOR_MAP_INTERLEAVE_NONE, CU_TENSOR_MAP_SWIZZLE_128B,
        CU_TENSOR_MAP_L2_PROMOTION_L2_128B, CU_TENSOR_MAP_FLOAT_OOB_FILL_NONE);
}

extern "C" void kernel_launch(void* const* d_in, const int* in_sizes, int n_in,
                              void* d_out, int out_size) {
    const float* x = (const float*)d_in[0];   // [8192, 4096]
    const float* w = (const float*)d_in[1];   // [4096, 4096]
    float* out = (float*)d_out;               // [8192, 4096]

    void *p_q = nullptr, *p_xh = nullptr;
    cudaGetSymbolAddress(&p_q, g_q);
    cudaGetSymbolAddress(&p_xh, g_xh);

    PFN_tmEnc enc = nullptr;
    cudaDriverEntryPointQueryResult qr;
    cudaGetDriverEntryPoint("cuTensorMapEncodeTiled", (void**)&enc, cudaEnableDefault, &qr);

    CUtensorMap tmA, tmB;
    make2d(enc, &tmA, p_xh, M);
    make2d(enc, &tmB, p_q, N);

    cudaFuncSetAttribute(gemm_kernel, cudaFuncAttributeMaxDynamicSharedMemorySize, SMEM_SIZE);

    const int conv_blocks = (int)(((size_t)M * K / 8) / 256);  // 16384
    prep_kernel<<<N + conv_blocks, 256>>>(w, x);
    gemm_kernel<<<dim3(N / BN, M / BM), 128, SMEM_SIZE>>>(tmA, tmB, out);
}

// round 8
// speedup vs baseline: 1.0585x; 1.0080x over previous
#include <cuda_runtime.h>
#include <cuda.h>
#include <cuda_fp16.h>
#include <cstdint>

// ============================================================================
// TernaryLinear: out[8192,4096] = x[8192,4096] @ (ternary(w)[4096,4096]).T
//
// out = (x @ q^T) * scale[col], q in {-1,0,1} exact in fp16; x -> fp16
// (u=2^-11 => ~3.5e-4 rel err, measured). fp32 accumulate in registers.
//
// R8: phase-staggered mbarrier waits. R7 measured a 116cyc/warp-chunk
// tensor gap ~= the 90cyc blocking TRYWAIT, implying the two co-resident
// CTAs stall in lockstep (shared tensor pipe equalizes progress). CTA pairs
// are (bid, bid+148), and 148 % 8 == 4, so (bid>>2)&1 differs within a
// pair: odd-phase CTAs wait for chunk i+1 at ks=1 (data issued 2 chunks
// ago, long complete), even-phase at ks=3. Co-resident warps now stall at
// points separated by ~512 cyc -> each covers the other's bubble.
// Otherwise identical to R7: TMA stage loads, 3-stage mbarrier pipeline,
// 2 CTAs/SM x 128 threads, 128x128 tiles, 64x64 warp tiles, cross-chunk
// ldmatrix prefetch, register frag double-buffering.
// ============================================================================

#define DINLINE __device__ __forceinline__

static constexpr int M = 8192, N = 4096, K = 4096;
static constexpr int BM = 128, BN = 128, BK = 64;
static constexpr int CHUNKS = K / BK;                  // 64
static constexpr int STAGES = 3;
static constexpr int STAGE_BYTES = (BM + BN) * BK * 2; // 32768
static constexpr int SMEM_STAGE0 = 1024;               // barriers live below
static constexpr int SMEM_SIZE = SMEM_STAGE0 + STAGES * STAGE_BYTES; // 99328

// scratch (device globals: allocation-free)
__device__ __half g_q[(size_t)N * K];     // ternary weights, fp16 exact
__device__ __half g_xh[(size_t)M * K];    // x in fp16
__device__ float  g_scale[N];

// ---------------------------------------------------------------------------
// helpers
// ---------------------------------------------------------------------------
DINLINE uint32_t smem_u32(const void* p) {
    uint32_t a;
    asm("{ .reg .u64 t; cvta.to.shared.u64 t, %1; cvt.u32.u64 %0, t; }" : "=r"(a) : "l"(p));
    return a;
}
DINLINE uint32_t elect_one() {
    uint32_t p;
    asm volatile("{ .reg .pred p; elect.sync _|p, 0xFFFFFFFF; selp.b32 %0, 1, 0, p; }" : "=r"(p));
    return p;
}
#define MBAR_INIT(a, c) asm volatile("mbarrier.init.shared.b64 [%0], %1;" :: "r"(a), "r"(c) : "memory")
#define MBAR_ARRIVE(a)  asm volatile("mbarrier.arrive.shared.b64 _, [%0];" :: "r"(a) : "memory")
#define MBAR_EXPECT_TX(a, b) asm volatile("mbarrier.arrive.expect_tx.shared.b64 _, [%0], %1;" :: "r"(a), "r"(b) : "memory")
#define MBAR_WAIT(a, ph) do {                                                     \
    uint32_t _m = (a), _p = (ph), _d;                                             \
    asm volatile("{ .reg .pred p; mbarrier.try_wait.parity.acquire.cta.shared::cta.b64 p, [%1], %2; selp.b32 %0,1,0,p; }" \
        : "=r"(_d) : "r"(_m), "r"(_p) : "memory");                                \
    if (!_d) {                                                                    \
        asm volatile("{ .reg .pred P1; W%=: mbarrier.try_wait.parity.acquire.cta.shared::cta.b64 P1, [%0], %1, 0x989680; @P1 bra.uni D%=; bra.uni W%=; D%=: }" \
            :: "r"(_m), "r"(_p) : "memory");                                      \
    }                                                                             \
} while (0)

#define TMA_LOAD_2D(smem, map, cx, cy, mbar)                                      \
    asm volatile("cp.async.bulk.tensor.2d.shared::cta.global.tile.mbarrier::complete_tx::bytes [%0], [%1, {%2, %3}], [%4];" \
        :: "r"(smem), "l"(map), "r"(cx), "r"(cy), "r"(mbar) : "memory")

DINLINE void ldsm4(uint32_t* r, uint32_t addr) {
    asm volatile("ldmatrix.sync.aligned.m8n8.x4.shared.b16 {%0,%1,%2,%3}, [%4];"
                 : "=r"(r[0]), "=r"(r[1]), "=r"(r[2]), "=r"(r[3]) : "r"(addr));
}
DINLINE void mma16816(float* c, const uint32_t* a, const uint32_t* b) {
    asm volatile(
        "mma.sync.aligned.m16n8k16.row.col.f32.f16.f16.f32 "
        "{%0,%1,%2,%3}, {%4,%5,%6,%7}, {%8,%9}, {%0,%1,%2,%3};"
        : "+f"(c[0]), "+f"(c[1]), "+f"(c[2]), "+f"(c[3])
        : "r"(a[0]), "r"(a[1]), "r"(a[2]), "r"(a[3]), "r"(b[0]), "r"(b[1]));
}

// ---------------------------------------------------------------------------
// Fused prep: blocks [0, N) quantize w rows (one-pass, row in registers);
// blocks [N, N + M*K/2048) convert x to fp16.
// ---------------------------------------------------------------------------
__global__ void __launch_bounds__(256) prep_kernel(const float* __restrict__ w,
                                                   const float* __restrict__ x) {
    if (blockIdx.x < (unsigned)N) {
        const int row = blockIdx.x, tid = threadIdx.x;
        const float4* wr = reinterpret_cast<const float4*>(w + (size_t)row * K);
        float4 v[4];
        float s = 0.f;
        #pragma unroll
        for (int t = 0; t < 4; t++) {
            v[t] = wr[tid + 256 * t];
            s += fabsf(v[t].x) + fabsf(v[t].y) + fabsf(v[t].z) + fabsf(v[t].w);
        }
        for (int o = 16; o; o >>= 1) s += __shfl_xor_sync(~0u, s, o);
        __shared__ float warp_s[8];
        __shared__ float sc;
        if ((tid & 31) == 0) warp_s[tid >> 5] = s;
        __syncthreads();
        if (tid == 0) {
            float t = 0.f;
            for (int i = 0; i < 8; i++) t += warp_s[i];
            float m = t * (1.f / (float)K);
            if (m < 1e-5f) m = 1e-5f;
            sc = m;
            g_scale[row] = m;
        }
        __syncthreads();
        const float inv = 1.f / sc;
        __half2* qr = reinterpret_cast<__half2*>(g_q + (size_t)row * K);
        #pragma unroll
        for (int t = 0; t < 4; t++) {
            float q0 = fminf(fmaxf(rintf(v[t].x * inv), -1.f), 1.f);
            float q1 = fminf(fmaxf(rintf(v[t].y * inv), -1.f), 1.f);
            float q2 = fminf(fmaxf(rintf(v[t].z * inv), -1.f), 1.f);
            float q3 = fminf(fmaxf(rintf(v[t].w * inv), -1.f), 1.f);
            qr[2 * (tid + 256 * t)]     = __floats2half2_rn(q0, q1);
            qr[2 * (tid + 256 * t) + 1] = __floats2half2_rn(q2, q3);
        }
    } else {
        size_t i = (size_t)(blockIdx.x - N) * 256 + threadIdx.x;  // 8 floats each
        const float4* x4 = reinterpret_cast<const float4*>(x);
        float4 a = x4[2 * i], b = x4[2 * i + 1];
        __half2 h0 = __floats2half2_rn(a.x, a.y);
        __half2 h1 = __floats2half2_rn(a.z, a.w);
        __half2 h2 = __floats2half2_rn(b.x, b.y);
        __half2 h3 = __floats2half2_rn(b.z, b.w);
        uint4 o;
        o.x = *reinterpret_cast<uint32_t*>(&h0);
        o.y = *reinterpret_cast<uint32_t*>(&h1);
        o.z = *reinterpret_cast<uint32_t*>(&h2);
        o.w = *reinterpret_cast<uint32_t*>(&h3);
        reinterpret_cast<uint4*>(g_xh)[i] = o;
    }
}

// ---------------------------------------------------------------------------
// GEMM: CTA 128x128, BK=64, 3-stage TMA+mbarrier pipeline, 4 warps (2m x 2n),
// 2 CTAs/SM. Warp tile 64x64 via mma.sync.m16n8k16, register frag
// double-buffering with cross-chunk prefetch. Full-wait position staggered
// by CTA phase ((bid>>2)&1) to decorrelate co-resident CTA stalls.
// ---------------------------------------------------------------------------
__global__ void __launch_bounds__(128, 2) gemm_kernel(
    const __grid_constant__ CUtensorMap tmA,
    const __grid_constant__ CUtensorMap tmB,
    float* __restrict__ out)        // [M,N] fp32
{
    extern __shared__ char smem[];
    const uint32_t sbase = smem_u32(smem);
    const int tid = threadIdx.x, lane = tid & 31, wid = tid >> 5;
    const int wm = wid >> 1, wn = wid & 1;     // warp tile: (wm*64, wn*64)
    const int mrow = blockIdx.y * BM;
    const int nbase = blockIdx.x * BN;
    const unsigned bid = blockIdx.y * gridDim.x + blockIdx.x;
    const int phase = (bid >> 2) & 1;          // differs within (b, b+148) pairs

    // barriers: full[0..2] at sbase+0,16,32 ; empty[0..2] at sbase+48,64,80
    const uint32_t FULL = sbase, EMPTY = sbase + 48;
    const uint32_t STAGE0 = sbase + SMEM_STAGE0;

    if (tid == 0) {
        #pragma unroll
        for (int s = 0; s < 3; s++) {
            MBAR_INIT(FULL + 16 * s, 1);
            MBAR_INIT(EMPTY + 16 * s, 128);
        }
    }
    __syncthreads();

    float acc[4][8][4];
    #pragma unroll
    for (int i = 0; i < 4; i++)
        #pragma unroll
        for (int j = 0; j < 8; j++)
            #pragma unroll
            for (int k = 0; k < 4; k++) acc[i][j][k] = 0.f;

    // ldmatrix lane coords
    const int arow = lane & 15, asel = lane >> 4;
    const int brow = (lane & 7) + ((lane >> 4) << 3), bsel = (lane >> 3) & 1;
    const int axor = arow & 7, bxor = brow & 7;

    // TMA stage issue (caller must be warp-uniform; elected lane only)
    auto issue_stage = [&](int s, int kc) {
        const uint32_t sA = STAGE0 + s * STAGE_BYTES;
        MBAR_EXPECT_TX(FULL + 16 * s, (uint32_t)STAGE_BYTES);
        TMA_LOAD_2D(sA,            &tmA, kc * BK, mrow,  FULL + 16 * s);
        TMA_LOAD_2D(sA + BM * 128, &tmB, kc * BK, nbase, FULL + 16 * s);
    };

    uint32_t af[2][4][4], bf[2][4][4];

    auto load_frags = [&](int s, int ks, int buf) {
        const uint32_t aB = STAGE0 + s * STAGE_BYTES;
        const uint32_t bB = aB + BM * 128;
        #pragma unroll
        for (int mt = 0; mt < 4; mt++) {
            const int row = wm * 64 + mt * 16 + arow;
            ldsm4(af[buf][mt], aB + row * 128 + (((ks * 2 + asel) ^ axor) << 4));
        }
        #pragma unroll
        for (int p = 0; p < 4; p++) {
            const int row = wn * 64 + p * 16 + brow;
            ldsm4(bf[buf][p], bB + row * 128 + (((ks * 2 + bsel) ^ bxor) << 4));
        }
    };

    // prologue: issue chunks 0 and 1; wait chunk 0; prefetch frags(0,0)
    if (wid == 0 && elect_one()) {
        issue_stage(0, 0);
        issue_stage(1, 1);
    }
    MBAR_WAIT(FULL + 0, 0);
    load_frags(0, 0, 0);

    for (int i = 0; i < CHUNKS; i++) {
        const int scur = i % STAGES;
        const int s1 = (i + 1) % STAGES;
        const uint32_t ph1 = ((i + 1) / 3) & 1;

        #pragma unroll
        for (int ks = 0; ks < 4; ks++) {
            const int b = ks & 1;
            if (ks == 1) {
                // odd-phase CTAs: wait for next chunk here (data issued 2
                // chunks ago -> long complete; decorrelates co-CTA stalls)
                if (phase && i + 1 < CHUNKS) {
                    MBAR_WAIT(FULL + 16 * s1, ph1);
                }
                if (i + 2 < CHUNKS && wid == ((i + 2) & 3)) {
                    // rotate TMA-issue duty across warps; WAR-gate on empty
                    if (elect_one()) {
                        const int s2 = (i + 2) % STAGES;
                        if (i + 2 >= STAGES) {
                            MBAR_WAIT(EMPTY + 16 * s2, (((i + 2) / 3) - 1) & 1);
                        }
                        issue_stage(s2, i + 2);
                    }
                }
            }
            if (ks < 3) {
                load_frags(scur, ks + 1, b ^ 1);
            } else if (i + 1 < CHUNKS) {
                if (!phase) MBAR_WAIT(FULL + 16 * s1, ph1);
                load_frags(s1, 0, b ^ 1);
            }
            #pragma unroll
            for (int mt = 0; mt < 4; mt++)
                #pragma unroll
                for (int nt = 0; nt < 8; nt++)
                    mma16816(acc[mt][nt], af[b][mt], bf[b][nt >> 1] + (nt & 1) * 2);
        }
        // all reads of stage scur complete (last ldsm consumed by ks=3 mma)
        MBAR_ARRIVE(EMPTY + 16 * scur);
    }

    // epilogue: scale columns, write fp32
    const int g = lane >> 2, qn = lane & 3;
    #pragma unroll
    for (int nt = 0; nt < 8; nt++) {
        const int col = wn * 64 + nt * 8 + qn * 2;
        const float2 s2 = *reinterpret_cast<const float2*>(&g_scale[nbase + col]);
        #pragma unroll
        for (int mt = 0; mt < 4; mt++) {
            const int row0 = mrow + wm * 64 + mt * 16 + g;
            float2 v0 = { acc[mt][nt][0] * s2.x, acc[mt][nt][1] * s2.y };
            float2 v1 = { acc[mt][nt][2] * s2.x, acc[mt][nt][3] * s2.y };
            *reinterpret_cast<float2*>(out + (size_t)row0 * N + nbase + col) = v0;
            *reinterpret_cast<float2*>(out + (size_t)(row0 + 8) * N + nbase + col) = v1;
        }
    }
}

// ---------------------------------------------------------------------------
// Host launch
// ---------------------------------------------------------------------------
typedef CUresult (*PFN_tmEnc)(CUtensorMap*, CUtensorMapDataType, cuuint32_t, void*,
                              const cuuint64_t*, const cuuint64_t*, const cuuint32_t*,
                              const cuuint32_t*, CUtensorMapInterleave, CUtensorMapSwizzle,
                              CUtensorMapL2promotion, CUtensorMapFloatOOBfill);

static void make2d(PFN_tmEnc enc, CUtensorMap* tm, void* ptr, uint64_t rows) {
    cuuint64_t dims[2] = {(cuuint64_t)K, rows};
    cuuint64_t strides[1] = {(cuuint64_t)K * 2};
    cuuint32_t box[2] = {64, 128};          // 64 halves = 128B x 128 rows
    cuuint32_t es[2] = {1, 1};
    enc(tm, CU_TENSOR_MAP_DATA_TYPE_BFLOAT16 /* 2-byte elems; layout-only */,
        2, ptr, dims, strides, box, es,
        CU_TENSOR_MAP_INTERLEAVE_NONE, CU_TENSOR_MAP_SWIZZLE_128B,
        CU_TENSOR_MAP_L2_PROMOTION_L2_128B, CU_TENSOR_MAP_FLOAT_OOB_FILL_NONE);
}

extern "C" void kernel_launch(void* const* d_in, const int* in_sizes, int n_in,
                              void* d_out, int out_size) {
    const float* x = (const float*)d_in[0];   // [8192, 4096]
    const float* w = (const float*)d_in[1];   // [4096, 4096]
    float* out = (float*)d_out;               // [8192, 4096]

    void *p_q = nullptr, *p_xh = nullptr;
    cudaGetSymbolAddress(&p_q, g_q);
    cudaGetSymbolAddress(&p_xh, g_xh);

    PFN_tmEnc enc = nullptr;
    cudaDriverEntryPointQueryResult qr;
    cudaGetDriverEntryPoint("cuTensorMapEncodeTiled", (void**)&enc, cudaEnableDefault, &qr);

    CUtensorMap tmA, tmB;
    make2d(enc, &tmA, p_xh, M);
    make2d(enc, &tmB, p_q, N);

    cudaFuncSetAttribute(gemm_kernel, cudaFuncAttributeMaxDynamicSharedMemorySize, SMEM_SIZE);

    const int conv_blocks = (int)(((size_t)M * K / 8) / 256);  // 16384
    prep_kernel<<<N + conv_blocks, 256>>>(w, x);
    gemm_kernel<<<dim3(N / BN, M / BM), 128, SMEM_SIZE>>>(tmA, tmB, out);
}